// round 10
// baseline (speedup 1.0000x reference)
#include <cuda_runtime.h>

#define NR 512
#define NZ 512
#define BUILD_BLOCKS 256

// Quad table: qt[ir*512+iz] = (tt[ir][iz], tt[ir][iz+1], tt[ir+1][iz], tt[ir+1][iz+1])
__device__ float4 g_qt[NR * NZ];
__device__ unsigned int g_ready = 0;  // builder blocks completed
__device__ unsigned int g_done  = 0;  // blocks retired (for self-reset)

// Fused: first BUILD_BLOCKS blocks build the quad table, every block interps.
// Device-side release/acquire barrier orders table writes before gathers.
__global__ void __launch_bounds__(256, 8) fused_interp_kernel(
    const float* __restrict__ r,
    const float* __restrict__ z,
    const float* __restrict__ tt,
    float* __restrict__ out,
    int n4)
{
    int tid = threadIdx.x;
    int bid = blockIdx.x;

    // ---- Build phase (blocks 0..255): 4 quads per thread, vectorized ----
    if (bid < BUILD_BLOCKS) {
        int t = bid * 256 + tid;      // 65536 threads
        int ir  = t >> 7;             // row 0..511
        int iz4 = (t & 127) << 2;     // 0,4,...,508
        if (ir < NR - 1) {
            const float* row0 = tt + ir * NZ + iz4;
            const float* row1 = row0 + NZ;
            float4 a = *reinterpret_cast<const float4*>(row0);
            float4 c = *reinterpret_cast<const float4*>(row1);
            bool last = (iz4 + 4 >= NZ);
            float b = last ? 0.0f : row0[4];
            float d = last ? 0.0f : row1[4];
            float a4[5] = {a.x, a.y, a.z, a.w, b};
            float c4[5] = {c.x, c.y, c.z, c.w, d};
            float4* q = &g_qt[ir * NZ + iz4];
#pragma unroll
            for (int k = 0; k < 4; k++) {
                if (iz4 + k >= NZ - 1) break;
                float4 v;
                v.x = a4[k]; v.y = a4[k + 1]; v.z = c4[k]; v.w = c4[k + 1];
                q[k] = v;
            }
        }
        __threadfence();        // publish table writes before the release count
        __syncthreads();
        if (tid == 0) atomicAdd(&g_ready, 1u);
    }

    // ---- Prolog: stream queries, compute cells (overlaps build) ----
    int i = bid * 256 + tid;
    bool active = (i < n4);

    float fr[4], fz[4];
    int   idx[4];
    if (active) {
        float4 rv = reinterpret_cast<const float4*>(r)[i];
        float4 zv = reinterpret_cast<const float4*>(z)[i];
        float rr[4] = {rv.x, rv.y, rv.z, rv.w};
        float zz[4] = {zv.x, zv.y, zv.z, zv.w};
#pragma unroll
        for (int k = 0; k < 4; k++) {
            float frf = fminf(fmaxf(floorf(rr[k]), 0.0f), (float)(NR - 2));
            float fzf = fminf(fmaxf(floorf(zz[k]), 0.0f), (float)(NZ - 2));
            fr[k] = rr[k] - frf;
            fz[k] = zz[k] - fzf;
            idx[k] = (((int)frf) << 9) + (int)fzf;
        }
    }

    // ---- Acquire: wait until the whole table is built ----
    if (tid == 0) {
        while (atomicAdd(&g_ready, 0u) < BUILD_BLOCKS) { }
    }
    __syncthreads();
    __threadfence();   // order gathers after the observed release

    // ---- Gather + FMA + store ----
    if (active) {
        float res[4];
#pragma unroll
        for (int k = 0; k < 4; k++) {
            float4 q = __ldg(&g_qt[idx[k]]);
            float wr1 = fr[k], wr0 = 1.0f - fr[k];
            float wz1 = fz[k], wz0 = 1.0f - fz[k];
            res[k] = q.x * (wr0 * wz0)
                   + q.z * (wr1 * wz0)
                   + q.y * (wr0 * wz1)
                   + q.w * (wr1 * wz1);
        }
        float4 o;
        o.x = res[0]; o.y = res[1]; o.z = res[2]; o.w = res[3];
        reinterpret_cast<float4*>(out)[i] = o;
    }

    // ---- Self-reset for graph replay: last block zeroes the counters ----
    __syncthreads();
    if (tid == 0) {
        unsigned int d = atomicAdd(&g_done, 1u);
        if (d == gridDim.x - 1) {
            g_ready = 0;
            g_done  = 0;
            __threadfence();
        }
    }
}

extern "C" void kernel_launch(void* const* d_in, const int* in_sizes, int n_in,
                              void* d_out, int out_size) {
    const float* r  = (const float*)d_in[0];
    const float* z  = (const float*)d_in[1];
    const float* tt = (const float*)d_in[2];
    float* out = (float*)d_out;

    int n = in_sizes[0];          // 20,000,000
    int n4 = n / 4;               // 5,000,000

    int threads = 256;
    int blocks = (n4 + threads - 1) / threads;   // 19532 >= BUILD_BLOCKS
    fused_interp_kernel<<<blocks, threads>>>(r, z, tt, out, n4);
}

// round 11
// speedup vs baseline: 1.2730x; 1.2730x over previous
#include <cuda_runtime.h>

#define NR 512
#define NZ 512

// Quad table: qt[ir*512+iz] = (tt[ir][iz], tt[ir][iz+1], tt[ir+1][iz], tt[ir+1][iz+1])
__device__ float4 g_qt[NR * NZ];

__global__ void __launch_bounds__(256) build_qt_kernel(const float* __restrict__ tt) {
    // Fire PDL completion immediately: interp launches and runs its prolog
    // while the table is being built; interp's griddepsync provides ordering.
    cudaTriggerProgrammaticLaunchCompletion();

    int t = blockIdx.x * blockDim.x + threadIdx.x;   // 262144
    int ir = t >> 9;
    int iz = t & 511;
    if (ir >= NR - 1 || iz >= NZ - 1) return;

    float q11 = __ldg(tt + t);
    float q12 = __ldg(tt + t + 1);
    float q21 = __ldg(tt + t + NZ);
    float q22 = __ldg(tt + t + NZ + 1);

    float4 v;
    v.x = q11; v.y = q12; v.z = q21; v.w = q22;
    g_qt[t] = v;
}

// 4 points/thread, regs=32, full occupancy — proven L1tex-floor config.
// Plain loads/stores (the .cs streaming hints measured ~1µs slower).
__global__ void __launch_bounds__(256) interp_kernel(
    const float* __restrict__ r,
    const float* __restrict__ z,
    float* __restrict__ out,
    int n4)
{
    int i = blockIdx.x * blockDim.x + threadIdx.x;
    if (i >= n4) {
        cudaGridDependencySynchronize();
        return;
    }

    float4 rv = reinterpret_cast<const float4*>(r)[i];
    float4 zv = reinterpret_cast<const float4*>(z)[i];

    float rr[4] = {rv.x, rv.y, rv.z, rv.w};
    float zz[4] = {zv.x, zv.y, zv.z, zv.w};

    float fr[4], fz[4];
    int   idx[4];
#pragma unroll
    for (int k = 0; k < 4; k++) {
        float frf = fminf(fmaxf(floorf(rr[k]), 0.0f), (float)(NR - 2));
        float fzf = fminf(fmaxf(floorf(zz[k]), 0.0f), (float)(NZ - 2));
        fr[k] = rr[k] - frf;
        fz[k] = zz[k] - fzf;
        idx[k] = (((int)frf) << 9) + (int)fzf;
    }

    // Wait for build_qt_kernel's writes to be visible before gathering.
    cudaGridDependencySynchronize();

    float res[4];
#pragma unroll
    for (int k = 0; k < 4; k++) {
        float4 q = __ldg(&g_qt[idx[k]]);
        float wr1 = fr[k], wr0 = 1.0f - fr[k];
        float wz1 = fz[k], wz0 = 1.0f - fz[k];
        res[k] = q.x * (wr0 * wz0)
               + q.z * (wr1 * wz0)
               + q.y * (wr0 * wz1)
               + q.w * (wr1 * wz1);
    }

    float4 o;
    o.x = res[0]; o.y = res[1]; o.z = res[2]; o.w = res[3];
    reinterpret_cast<float4*>(out)[i] = o;
}

extern "C" void kernel_launch(void* const* d_in, const int* in_sizes, int n_in,
                              void* d_out, int out_size) {
    const float* r  = (const float*)d_in[0];
    const float* z  = (const float*)d_in[1];
    const float* tt = (const float*)d_in[2];
    float* out = (float*)d_out;

    int n = in_sizes[0];          // 20,000,000
    int n4 = n / 4;               // 5,000,000

    build_qt_kernel<<<(NR * NZ) / 256, 256>>>(tt);

    int threads = 256;
    int blocks = (n4 + threads - 1) / threads;

    // PDL: interp launches as soon as build fires its trigger; device-side
    // griddepsync orders the quad-table reads.
    cudaLaunchAttribute attrs[1];
    attrs[0].id = cudaLaunchAttributeProgrammaticStreamSerialization;
    attrs[0].val.programmaticStreamSerializationAllowed = 1;

    cudaLaunchConfig_t cfg = {};
    cfg.gridDim = dim3((unsigned)blocks);
    cfg.blockDim = dim3((unsigned)threads);
    cfg.dynamicSmemBytes = 0;
    cfg.stream = 0;
    cfg.attrs = attrs;
    cfg.numAttrs = 1;

    cudaLaunchKernelEx(&cfg, interp_kernel, r, z, out, n4);
}